// round 5
// baseline (speedup 1.0000x reference)
#include <cuda_runtime.h>
#include <math_constants.h>

// Heatmaps_57363583205469: 3x3 max-pool peak mask + sigmoid gating.
//   keep = (maxpool3x3(h) == h) && (sigmoid(h) > 0.05)
//   out  = keep ? sigmoid(h) : 0
// Shapes: [16, 17, 512, 512] fp32 -> 272 planes of 512x512.
//
// Strategy: single streaming pass. Each thread owns 4 contiguous columns
// (float4). Horizontal 3-max built with warp shuffles (warp-edge lanes do one
// scalar L1-cached load). Vertical 3-max via a rolling 3-row register window
// while walking a 64-row strip. Each element read once from DRAM (+2 halo
// rows per strip = 3% overhead). No smem, no barriers.

#define W 512
#define H 512
#define ROWS_PER_BLOCK 64
// logit(0.05f) computed in double precision: -ln(1/0.05000000074505806 - 1)
#define XTHRESH (-2.9444389643f)

__device__ __forceinline__ float4 row_hmax(const float* __restrict__ row,
                                           int c0, int lane, float4& v)
{
    v = __ldg(reinterpret_cast<const float4*>(row + c0));
    float l = __shfl_up_sync(0xffffffffu, v.w, 1);
    float r = __shfl_down_sync(0xffffffffu, v.x, 1);
    if (lane == 0)  l = (c0 == 0)       ? -CUDART_INF_F : __ldg(row + c0 - 1);
    if (lane == 31) r = (c0 + 4 >= W)   ? -CUDART_INF_F : __ldg(row + c0 + 4);
    float4 h;
    h.x = fmaxf(fmaxf(l,   v.x), v.y);
    h.y = fmaxf(fmaxf(v.x, v.y), v.z);
    h.z = fmaxf(fmaxf(v.y, v.z), v.w);
    h.w = fmaxf(fmaxf(v.z, v.w), r);
    return h;
}

__device__ __forceinline__ float peak_val(float m, float v)
{
    // sigmoid via fast EX2 + RCP (2 MUFU) — rel err ~1e-6, hides under DRAM.
    float s = __fdividef(1.0f, 1.0f + __expf(-v));
    return (m == v && v > XTHRESH) ? s : 0.0f;
}

__global__ void __launch_bounds__(128)
Heatmaps_57363583205469_kernel(const float* __restrict__ in,
                               float* __restrict__ out)
{
    const int plane = blockIdx.y;                 // 0..271  (B*K planes)
    const int strip = blockIdx.x;                 // 0..7    (64-row strips)
    const int lane  = threadIdx.x & 31;
    const int c0    = threadIdx.x << 2;           // 4 cols per thread

    const float* __restrict__ base  = in  + (size_t)plane * (W * H);
    float*       __restrict__ obase = out + (size_t)plane * (W * H);
    const int r0 = strip * ROWS_PER_BLOCK;

    const float4 ninf = make_float4(-CUDART_INF_F, -CUDART_INF_F,
                                    -CUDART_INF_F, -CUDART_INF_F);

    float4 v_curr, v_next, v_scratch;
    float4 h_prev, h_curr, h_next;

    h_prev = (r0 == 0) ? ninf
                       : row_hmax(base + (size_t)(r0 - 1) * W, c0, lane, v_scratch);
    h_curr = row_hmax(base + (size_t)r0 * W, c0, lane, v_curr);

    #pragma unroll 4
    for (int r = r0; r < r0 + ROWS_PER_BLOCK; ++r) {
        if (r + 1 < H) {
            h_next = row_hmax(base + (size_t)(r + 1) * W, c0, lane, v_next);
        } else {
            h_next = ninf;
            v_next = ninf;
        }

        float4 o;
        o.x = peak_val(fmaxf(fmaxf(h_prev.x, h_curr.x), h_next.x), v_curr.x);
        o.y = peak_val(fmaxf(fmaxf(h_prev.y, h_curr.y), h_next.y), v_curr.y);
        o.z = peak_val(fmaxf(fmaxf(h_prev.z, h_curr.z), h_next.z), v_curr.z);
        o.w = peak_val(fmaxf(fmaxf(h_prev.w, h_curr.w), h_next.w), v_curr.w);

        *reinterpret_cast<float4*>(obase + (size_t)r * W + c0) = o;

        h_prev = h_curr;
        h_curr = h_next;
        v_curr = v_next;
    }
}

extern "C" void kernel_launch(void* const* d_in, const int* in_sizes, int n_in,
                              void* d_out, int out_size)
{
    const float* in  = (const float*)d_in[0];
    float*       out = (float*)d_out;
    const int planes = in_sizes[0] / (W * H);     // 16 * 17 = 272

    dim3 grid(H / ROWS_PER_BLOCK, planes);
    Heatmaps_57363583205469_kernel<<<grid, 128>>>(in, out);
}